// round 4
// baseline (speedup 1.0000x reference)
#include <cuda_runtime.h>
#include <cstdint>

#define TAGS 22
#define START_TAG 20
#define END_TAG 21
#define SEQ 512
#define BATCH 128
#define HID 1024

// scratch for projected features (static __device__ per allocation rules)
__device__ float g_feats[(size_t)BATCH * SEQ * TAGS];

// ---------------------------------------------------------------------------
// GEMM: g_feats[m][t] = sum_h X[m][h] * W[t][h] + bias[t]   (m = b*SEQ+s)
// Tile: 128 rows x 24 tags (22 real), K-chunks of 32. 128 threads:
//   tg = tid&7 -> 3 tags each, rg = tid>>3 -> 8 rows each (rows rg+16*i).
// Smem rows padded to 36 floats so k-major float4 LDS.128 stays 16B-aligned.
// ---------------------------------------------------------------------------
#define MT 128
#define KC 32
#define TP 24
#define PAD 36

__global__ __launch_bounds__(128) void gemm_kernel(
    const float* __restrict__ X, const float* __restrict__ W,
    const float* __restrict__ bias)
{
    __shared__ float Xs[MT][PAD];
    __shared__ float Ws[TP][PAD];
    const int tid = threadIdx.x;
    const int tg = tid & 7;    // 0..7
    const int rg = tid >> 3;   // 0..15
    const int row0 = blockIdx.x * MT;

    float acc[8][3];
#pragma unroll
    for (int i = 0; i < 8; i++)
#pragma unroll
        for (int j = 0; j < 3; j++) acc[i][j] = 0.f;

    for (int kc = 0; kc < HID; kc += KC) {
        __syncthreads();
        // X tile: 128 rows x 32 floats = 1024 float4, 8 per thread, coalesced
#pragma unroll
        for (int i = 0; i < 8; i++) {
            int idx = i * 128 + tid;
            int r = idx >> 3;
            int k4 = idx & 7;
            float4 v = *(const float4*)(X + (size_t)(row0 + r) * HID + kc + k4 * 4);
            *(float4*)&Xs[r][k4 * 4] = v;
        }
        // W tile: 24 x 32 = 192 float4 (rows >= 22 zero-filled)
        {
            int idx = tid;
            if (idx < 64) idx += 128;   // threads 0..63 do a second slot
            // every thread covers exactly one of 192 slots except 64..127 cover theirs
        }
#pragma unroll
        for (int i = 0; i < 2; i++) {
            int idx = i * 128 + tid;
            if (idx < 192) {
                int t = idx >> 3;
                int k4 = idx & 7;
                float4 v = make_float4(0.f, 0.f, 0.f, 0.f);
                if (t < TAGS) v = *(const float4*)(W + (size_t)t * HID + kc + k4 * 4);
                *(float4*)&Ws[t][k4 * 4] = v;
            }
        }
        __syncthreads();
#pragma unroll
        for (int k4 = 0; k4 < KC / 4; k4++) {
            float4 xv[8], wv[3];
#pragma unroll
            for (int i = 0; i < 8; i++) xv[i] = *(const float4*)&Xs[rg + 16 * i][k4 * 4];
#pragma unroll
            for (int j = 0; j < 3; j++) wv[j] = *(const float4*)&Ws[tg * 3 + j][k4 * 4];
#pragma unroll
            for (int i = 0; i < 8; i++)
#pragma unroll
                for (int j = 0; j < 3; j++) {
                    acc[i][j] = fmaf(xv[i].x, wv[j].x, acc[i][j]);
                    acc[i][j] = fmaf(xv[i].y, wv[j].y, acc[i][j]);
                    acc[i][j] = fmaf(xv[i].z, wv[j].z, acc[i][j]);
                    acc[i][j] = fmaf(xv[i].w, wv[j].w, acc[i][j]);
                }
        }
    }

    float bb[3];
#pragma unroll
    for (int j = 0; j < 3; j++) {
        int t = tg * 3 + j;
        bb[j] = (t < TAGS) ? bias[t] : 0.f;
    }
#pragma unroll
    for (int i = 0; i < 8; i++) {
        int r = row0 + rg + 16 * i;
#pragma unroll
        for (int j = 0; j < 3; j++) {
            int t = tg * 3 + j;
            if (t < TAGS) g_feats[(size_t)r * TAGS + t] = acc[i][j] + bb[j];
        }
    }
}

// ---------------------------------------------------------------------------
// CRF scan + score: one warp per batch.
// lane j owns alpha[j]; E[t][j]=exp(trans[t][j]) lives in lane t's registers.
// Step: p_j = exp(alpha_j - m_lag2); alpha_t' = feat_t + m + log(sum_j E[t][j] p_j)
// The warp max-reduce for the normalizer runs 2 steps ahead (off critical path).
// ---------------------------------------------------------------------------
__global__ __launch_bounds__(32) void scan_kernel(
    const int* __restrict__ tags, const int* __restrict__ lengths,
    const float* __restrict__ trans, float* __restrict__ out)
{
    __shared__ float fs[SEQ * TAGS];   // 45056 B: this batch's feats
    __shared__ float ts[TAGS * TAGS];  // 1936 B: transition matrix
    const unsigned FULL = 0xffffffffu;
    const int b = blockIdx.x;
    const int lane = threadIdx.x;
    const int len = lengths[b];

    for (int i = lane; i < TAGS * TAGS; i += 32) ts[i] = trans[i];
    {
        const float4* src = (const float4*)(g_feats + (size_t)b * SEQ * TAGS);
        float4* dst = (float4*)fs;
        const int n4 = (len * TAGS + 3) >> 2;
#pragma unroll 4
        for (int i = lane; i < n4; i += 32) dst[i] = src[i];
    }
    __syncwarp();

    float E[TAGS];
#pragma unroll
    for (int j = 0; j < TAGS; j++) E[j] = 0.f;
    float endr = 0.f;
    float alpha = -1e30f;
    if (lane < TAGS) {
#pragma unroll
        for (int j = 0; j < TAGS; j++) E[j] = __expf(ts[lane * TAGS + j]);
        endr = ts[END_TAG * TAGS + lane];
        alpha = (lane == START_TAG) ? 0.f : -1e30f;
    }

    float m_use = 0.f, m_mid = 0.f;  // max(alpha0) = 0 exactly

    for (int i = 0; i < len; i++) {
        float feat = (lane < TAGS) ? fs[i * TAGS + lane] : 0.f;
        float p = __expf(alpha - m_use);
        float a0 = 0.f, a1 = 0.f, a2 = 0.f, a3 = 0.f;
        a0 = fmaf(E[0],  __shfl_sync(FULL, p, 0),  a0);
        a1 = fmaf(E[1],  __shfl_sync(FULL, p, 1),  a1);
        a2 = fmaf(E[2],  __shfl_sync(FULL, p, 2),  a2);
        a3 = fmaf(E[3],  __shfl_sync(FULL, p, 3),  a3);
        a0 = fmaf(E[4],  __shfl_sync(FULL, p, 4),  a0);
        a1 = fmaf(E[5],  __shfl_sync(FULL, p, 5),  a1);
        a2 = fmaf(E[6],  __shfl_sync(FULL, p, 6),  a2);
        a3 = fmaf(E[7],  __shfl_sync(FULL, p, 7),  a3);
        a0 = fmaf(E[8],  __shfl_sync(FULL, p, 8),  a0);
        a1 = fmaf(E[9],  __shfl_sync(FULL, p, 9),  a1);
        a2 = fmaf(E[10], __shfl_sync(FULL, p, 10), a2);
        a3 = fmaf(E[11], __shfl_sync(FULL, p, 11), a3);
        a0 = fmaf(E[12], __shfl_sync(FULL, p, 12), a0);
        a1 = fmaf(E[13], __shfl_sync(FULL, p, 13), a1);
        a2 = fmaf(E[14], __shfl_sync(FULL, p, 14), a2);
        a3 = fmaf(E[15], __shfl_sync(FULL, p, 15), a3);
        a0 = fmaf(E[16], __shfl_sync(FULL, p, 16), a0);
        a1 = fmaf(E[17], __shfl_sync(FULL, p, 17), a1);
        a2 = fmaf(E[18], __shfl_sync(FULL, p, 18), a2);
        a3 = fmaf(E[19], __shfl_sync(FULL, p, 19), a3);
        a0 = fmaf(E[20], __shfl_sync(FULL, p, 20), a0);
        a1 = fmaf(E[21], __shfl_sync(FULL, p, 21), a1);

        // normalizer for step i+2 (independent of the exp/dot/log chain above)
        float m_new = alpha;
#pragma unroll
        for (int o = 16; o; o >>= 1) m_new = fmaxf(m_new, __shfl_xor_sync(FULL, m_new, o));

        float s = (a0 + a1) + (a2 + a3);
        if (lane < TAGS) alpha = feat + m_use + __logf(fmaxf(s, 1e-37f));
        m_use = m_mid;
        m_mid = m_new;
    }

    // end transition + partition function Z
    alpha += (lane < TAGS) ? endr : 0.f;
    float mz = alpha;
#pragma unroll
    for (int o = 16; o; o >>= 1) mz = fmaxf(mz, __shfl_xor_sync(FULL, mz, o));
    float pz = __expf(alpha - mz);
#pragma unroll
    for (int o = 16; o; o >>= 1) pz += __shfl_xor_sync(FULL, pz, o);
    float Z = mz + __logf(pz);

    // gold-path score
    float sc = 0.f;
    const int* tgp = tags + b * SEQ;
    for (int i = lane; i < len; i += 32) {
        int cur = tgp[i];
        int prev = (i == 0) ? START_TAG : tgp[i - 1];
        sc += fs[i * TAGS + cur] + ts[cur * TAGS + prev];
    }
#pragma unroll
    for (int o = 16; o; o >>= 1) sc += __shfl_xor_sync(FULL, sc, o);

    if (lane == 0) {
        sc += ts[END_TAG * TAGS + tgp[len - 1]];
        out[b] = Z - sc;
    }
}

// ---------------------------------------------------------------------------
extern "C" void kernel_launch(void* const* d_in, const int* in_sizes, int n_in,
                              void* d_out, int out_size)
{
    const float* X       = (const float*)d_in[0];  // sentence_feats [128,512,1024]
    const int*   tags    = (const int*)  d_in[1];  // [128,512]
    const int*   lengths = (const int*)  d_in[2];  // [128]
    const float* W       = (const float*)d_in[3];  // [22,1024]
    const float* bias    = (const float*)d_in[4];  // [22]
    const float* trans   = (const float*)d_in[5];  // [22,22]
    float* out = (float*)d_out;                    // [128]

    gemm_kernel<<<(BATCH * SEQ) / MT, 128>>>(X, W, bias);
    scan_kernel<<<BATCH, 32>>>(tags, lengths, trans, out);
}

// round 5
// speedup vs baseline: 1.1915x; 1.1915x over previous
#include <cuda_runtime.h>
#include <cstdint>

#define TAGS 22
#define START_TAG 20
#define END_TAG 21
#define SEQ 512
#define BATCH 128
#define HID 1024

// scratch (static __device__ per allocation rules)
__device__ float g_ef[(size_t)BATCH * SEQ * TAGS];    // exp(feats), packed 22
__device__ float g_raw[(size_t)BATCH * SEQ * TAGS];   // raw feats for gold score

// ---------------- packed f32x2 helpers (Blackwell) -------------------------
__device__ __forceinline__ unsigned long long ffma2(unsigned long long a,
                                                    unsigned long long b,
                                                    unsigned long long c) {
    unsigned long long d;
    asm("fma.rn.f32x2 %0, %1, %2, %3;" : "=l"(d) : "l"(a), "l"(b), "l"(c));
    return d;
}
__device__ __forceinline__ unsigned long long fadd2(unsigned long long a,
                                                    unsigned long long b) {
    unsigned long long d;
    asm("add.rn.f32x2 %0, %1, %2;" : "=l"(d) : "l"(a), "l"(b));
    return d;
}
__device__ __forceinline__ unsigned long long pack2(float lo, float hi) {
    unsigned long long d;
    asm("mov.b64 %0, {%1, %2};" : "=l"(d) : "f"(lo), "f"(hi));
    return d;
}
__device__ __forceinline__ float2 unpack2(unsigned long long v) {
    float2 r;
    asm("mov.b64 {%0, %1}, %2;" : "=f"(r.x), "=f"(r.y) : "l"(v));
    return r;
}

// ---------------------------------------------------------------------------
// GEMM: feats[m][t] = sum_h X[m][h] * W[t][h] + bias[t]; writes raw + exp().
// 128 rows x 24 tags tile, K-chunks of 32, packed-f32x2 inner product.
// ---------------------------------------------------------------------------
#define MT 128
#define KC 32
#define TP 24
#define PAD 36

__global__ __launch_bounds__(128) void gemm_kernel(
    const float* __restrict__ X, const float* __restrict__ W,
    const float* __restrict__ bias)
{
    __shared__ __align__(16) float Xs[MT][PAD];
    __shared__ __align__(16) float Ws[TP][PAD];
    const int tid = threadIdx.x;
    const int tg = tid & 7;    // 0..7  -> 3 tags each
    const int rg = tid >> 3;   // 0..15 -> 8 rows each
    const int row0 = blockIdx.x * MT;

    unsigned long long acc2[8][3];
#pragma unroll
    for (int i = 0; i < 8; i++)
#pragma unroll
        for (int j = 0; j < 3; j++) acc2[i][j] = 0ull;

    for (int kc = 0; kc < HID; kc += KC) {
        __syncthreads();
#pragma unroll
        for (int i = 0; i < 8; i++) {
            int idx = i * 128 + tid;
            int r = idx >> 3;
            int k4 = idx & 7;
            float4 v = *(const float4*)(X + (size_t)(row0 + r) * HID + kc + k4 * 4);
            *(float4*)&Xs[r][k4 * 4] = v;
        }
#pragma unroll
        for (int i = 0; i < 2; i++) {
            int idx = i * 128 + tid;
            if (idx < 192) {
                int t = idx >> 3;
                int k4 = idx & 7;
                float4 v = make_float4(0.f, 0.f, 0.f, 0.f);
                if (t < TAGS) v = *(const float4*)(W + (size_t)t * HID + kc + k4 * 4);
                *(float4*)&Ws[t][k4 * 4] = v;
            }
        }
        __syncthreads();
#pragma unroll
        for (int k4 = 0; k4 < KC / 4; k4++) {
            ulonglong2 xv[8], wv[3];
#pragma unroll
            for (int i = 0; i < 8; i++)
                xv[i] = *(const ulonglong2*)&Xs[rg + 16 * i][k4 * 4];
#pragma unroll
            for (int j = 0; j < 3; j++)
                wv[j] = *(const ulonglong2*)&Ws[tg * 3 + j][k4 * 4];
#pragma unroll
            for (int i = 0; i < 8; i++)
#pragma unroll
                for (int j = 0; j < 3; j++) {
                    acc2[i][j] = ffma2(xv[i].x, wv[j].x, acc2[i][j]);
                    acc2[i][j] = ffma2(xv[i].y, wv[j].y, acc2[i][j]);
                }
        }
    }

    float bb[3];
#pragma unroll
    for (int j = 0; j < 3; j++) {
        int t = tg * 3 + j;
        bb[j] = (t < TAGS) ? bias[t] : 0.f;
    }
#pragma unroll
    for (int i = 0; i < 8; i++) {
        size_t r = row0 + rg + 16 * i;
#pragma unroll
        for (int j = 0; j < 3; j++) {
            int t = tg * 3 + j;
            if (t < TAGS) {
                float2 f = unpack2(acc2[i][j]);
                float raw = f.x + f.y + bb[j];
                g_raw[r * TAGS + t] = raw;
                g_ef[r * TAGS + t] = __expf(raw);
            }
        }
    }
}

// ---------------------------------------------------------------------------
// CRF scan in scaled-probability space. One warp per batch.
// State p_t >= 0 in lane t; broadcast via smem double buffer (LDS.128 x6).
// Step: p'_t = exp(feat_t) * r * sum_j E[t][j] p_j ; r = 2^-e lane-uniform,
// recomputed every 2nd step from the shared p vector (no communication).
// Z = log(sum_t p_t * exp(trans[END][t])) + ke*ln2.
// ---------------------------------------------------------------------------
__global__ __launch_bounds__(32) void scan_kernel(
    const int* __restrict__ tags, const int* __restrict__ lengths,
    const float* __restrict__ trans, float* __restrict__ out)
{
    __shared__ __align__(16) float pbuf[2][24];
    __shared__ float fs[SEQ * TAGS];   // exp(feats) for this batch, packed 22
    __shared__ float ts[TAGS * TAGS];
    const unsigned FULL = 0xffffffffu;
    const int b = blockIdx.x;
    const int lane = threadIdx.x;
    const int len = lengths[b];

    for (int i = lane; i < TAGS * TAGS; i += 32) ts[i] = trans[i];
    {
        const float4* src = (const float4*)(g_ef + (size_t)b * SEQ * TAGS);
        float4* dst = (float4*)fs;
        const int n4 = (len * TAGS + 3) >> 2;
#pragma unroll 4
        for (int i = lane; i < n4; i += 32) dst[i] = src[i];
    }
    if (lane < 24) {
        pbuf[0][lane] = (lane == START_TAG) ? 1.f : 0.f;
        pbuf[1][lane] = 0.f;
    }
    __syncwarp();

    // E rows packed as f32x2 pairs; lane t holds E[t][0..23] (pads zero)
    unsigned long long E2[12];
    float endr = 0.f;
#pragma unroll
    for (int jp = 0; jp < 12; jp++) E2[jp] = 0ull;
    if (lane < TAGS) {
#pragma unroll
        for (int jp = 0; jp < 11; jp++) {
            float lo = __expf(ts[lane * TAGS + 2 * jp]);
            float hi = (2 * jp + 1 < TAGS) ? __expf(ts[lane * TAGS + 2 * jp + 1]) : 0.f;
            E2[jp] = pack2(lo, hi);
        }
        endr = ts[END_TAG * TAGS + lane];
    }

    float pcur = 0.f;
    int ke = 0;

    for (int i = 0; i < len; i++) {
        __syncwarp();
        const ulonglong2* pb = (const ulonglong2*)pbuf[i & 1];
        ulonglong2 v0 = pb[0], v1 = pb[1], v2 = pb[2],
                   v3 = pb[3], v4 = pb[4], v5 = pb[5];
        float ef = (lane < TAGS) ? fs[i * TAGS + lane] : 0.f;

        float r = 1.0f;
        if (i & 1) {  // renormalize: lane-uniform from shared data
            float2 a0 = unpack2(v0.x), a1 = unpack2(v0.y);
            float2 a2 = unpack2(v1.x), a3 = unpack2(v1.y);
            float2 a4 = unpack2(v2.x), a5 = unpack2(v2.y);
            float2 a6 = unpack2(v3.x), a7 = unpack2(v3.y);
            float2 a8 = unpack2(v4.x), a9 = unpack2(v4.y);
            float2 aa = unpack2(v5.x), ab = unpack2(v5.y);
            float m0 = fmaxf(fmaxf(fmaxf(a0.x, a0.y), fmaxf(a1.x, a1.y)),
                             fmaxf(fmaxf(a2.x, a2.y), fmaxf(a3.x, a3.y)));
            float m1 = fmaxf(fmaxf(fmaxf(a4.x, a4.y), fmaxf(a5.x, a5.y)),
                             fmaxf(fmaxf(a6.x, a6.y), fmaxf(a7.x, a7.y)));
            float m2 = fmaxf(fmaxf(fmaxf(a8.x, a8.y), fmaxf(a9.x, a9.y)),
                             fmaxf(fmaxf(aa.x, aa.y), fmaxf(ab.x, ab.y)));
            float m = fmaxf(m0, fmaxf(m1, m2));
            int eb = (__float_as_int(m) >> 23) & 255;
            ke += eb - 127;
            r = __int_as_float((254 - eb) << 23);  // 2^-(eb-127)
        }

        unsigned long long q0 = ffma2(E2[0], v0.x, 0ull);
        unsigned long long q1 = ffma2(E2[1], v0.y, 0ull);
        unsigned long long q2 = ffma2(E2[2], v1.x, 0ull);
        unsigned long long q3 = ffma2(E2[3], v1.y, 0ull);
        q0 = ffma2(E2[4], v2.x, q0);
        q1 = ffma2(E2[5], v2.y, q1);
        q2 = ffma2(E2[6], v3.x, q2);
        q3 = ffma2(E2[7], v3.y, q3);
        q0 = ffma2(E2[8], v4.x, q0);
        q1 = ffma2(E2[9], v4.y, q1);
        q2 = ffma2(E2[10], v5.x, q2);
        q3 = ffma2(E2[11], v5.y, q3);
        unsigned long long s2 = fadd2(fadd2(q0, q1), fadd2(q2, q3));
        float2 sf = unpack2(s2);
        float pn = (ef * r) * (sf.x + sf.y);

        if (lane < TAGS) pbuf[(i + 1) & 1][lane] = pn;
        pcur = pn;
    }

    // Z = log(sum p * exp(end_row)) + ke*ln2
    float val = (lane < TAGS) ? pcur * __expf(endr) : 0.f;
#pragma unroll
    for (int o = 16; o; o >>= 1) val += __shfl_xor_sync(FULL, val, o);
    float Z = __logf(val) + (float)ke * 0.69314718056f;

    // gold-path score (raw feats from global, transitions from smem)
    float sc = 0.f;
    const int* tgp = tags + b * SEQ;
    const float* rawb = g_raw + (size_t)b * SEQ * TAGS;
    for (int i = lane; i < len; i += 32) {
        int cur = tgp[i];
        int prev = (i == 0) ? START_TAG : tgp[i - 1];
        sc += rawb[i * TAGS + cur] + ts[cur * TAGS + prev];
    }
#pragma unroll
    for (int o = 16; o; o >>= 1) sc += __shfl_xor_sync(FULL, sc, o);

    if (lane == 0) {
        sc += ts[END_TAG * TAGS + tgp[len - 1]];
        out[b] = Z - sc;
    }
}

// ---------------------------------------------------------------------------
extern "C" void kernel_launch(void* const* d_in, const int* in_sizes, int n_in,
                              void* d_out, int out_size)
{
    const float* X       = (const float*)d_in[0];  // [128,512,1024]
    const int*   tags    = (const int*)  d_in[1];  // [128,512]
    const int*   lengths = (const int*)  d_in[2];  // [128]
    const float* W       = (const float*)d_in[3];  // [22,1024]
    const float* bias    = (const float*)d_in[4];  // [22]
    const float* trans   = (const float*)d_in[5];  // [22,22]
    float* out = (float*)d_out;                    // [128]

    gemm_kernel<<<(BATCH * SEQ) / MT, 128>>>(X, W, bias);
    scan_kernel<<<BATCH, 32>>>(tags, lengths, trans, out);
}

// round 6
// speedup vs baseline: 1.2372x; 1.0384x over previous
#include <cuda_runtime.h>
#include <cstdint>

#define TAGS 22
#define START_TAG 20
#define END_TAG 21
#define SEQ 512
#define BATCH 128
#define HID 1024

// scratch (static __device__ per allocation rules)
__device__ float g_ef[(size_t)BATCH * SEQ * TAGS];    // exp(feats), packed 22
__device__ float g_raw[(size_t)BATCH * SEQ * TAGS];   // raw feats for gold score

// ---------------- packed f32x2 helpers (Blackwell) -------------------------
__device__ __forceinline__ unsigned long long ffma2(unsigned long long a,
                                                    unsigned long long b,
                                                    unsigned long long c) {
    unsigned long long d;
    asm("fma.rn.f32x2 %0, %1, %2, %3;" : "=l"(d) : "l"(a), "l"(b), "l"(c));
    return d;
}
__device__ __forceinline__ unsigned long long fadd2(unsigned long long a,
                                                    unsigned long long b) {
    unsigned long long d;
    asm("add.rn.f32x2 %0, %1, %2;" : "=l"(d) : "l"(a), "l"(b));
    return d;
}
__device__ __forceinline__ unsigned long long pack2(float lo, float hi) {
    unsigned long long d;
    asm("mov.b64 %0, {%1, %2};" : "=l"(d) : "f"(lo), "f"(hi));
    return d;
}
__device__ __forceinline__ float2 unpack2(unsigned long long v) {
    float2 r;
    asm("mov.b64 {%0, %1}, %2;" : "=f"(r.x), "=f"(r.y) : "l"(v));
    return r;
}

// ---------------- cp.async helpers -----------------------------------------
__device__ __forceinline__ void cp16(uint32_t dst, const void* src) {
    asm volatile("cp.async.cg.shared.global [%0], [%1], 16;\n" ::
                 "r"(dst), "l"(src));
}
__device__ __forceinline__ void cp16p(uint32_t dst, const void* src, int keep) {
    // keep==0 -> copy 0 source bytes, zero-fill the 16B destination
    asm volatile("cp.async.cg.shared.global [%0], [%1], 16, %2;\n" ::
                 "r"(dst), "l"(src), "r"(keep ? 16 : 0));
}
__device__ __forceinline__ void cp_commit() {
    asm volatile("cp.async.commit_group;\n");
}
template <int N>
__device__ __forceinline__ void cp_wait() {
    asm volatile("cp.async.wait_group %0;\n" :: "n"(N));
}

// ---------------------------------------------------------------------------
// GEMM: feats[m][t] = sum_h X[m][h] * W[t][h] + bias[t]; writes raw + exp().
// 128 rows x 24 tags tile, K-chunks of 32, 2-stage cp.async pipeline.
// ---------------------------------------------------------------------------
#define MT 128
#define KC 32
#define TP 24
#define PAD 36
#define NKC (HID / KC)   // 32

__global__ __launch_bounds__(128) void gemm_kernel(
    const float* __restrict__ X, const float* __restrict__ W,
    const float* __restrict__ bias)
{
    __shared__ __align__(16) float Xs[2][MT][PAD];   // 2*18432 B
    __shared__ __align__(16) float Ws[2][TP][PAD];   // 2*3456 B
    const int tid = threadIdx.x;
    const int tg = tid & 7;    // 0..7  -> 3 tags each
    const int rg = tid >> 3;   // 0..15 -> 8 rows each
    const int row0 = blockIdx.x * MT;

    // per-thread load slots (constant across stages)
    const int xr = tid >> 3;          // via idx = i*128+tid below
    (void)xr;
    uint32_t xs_base = (uint32_t)__cvta_generic_to_shared(&Xs[0][0][0]);
    uint32_t ws_base = (uint32_t)__cvta_generic_to_shared(&Ws[0][0][0]);
    const uint32_t stageX = MT * PAD * 4;  // bytes per X stage
    const uint32_t stageW = TP * PAD * 4;

    auto load_stage = [&](int st, int kc) {
#pragma unroll
        for (int i = 0; i < 8; i++) {
            int idx = i * 128 + tid;
            int r = idx >> 3;
            int k4 = idx & 7;
            cp16(xs_base + st * stageX + (r * PAD + k4 * 4) * 4,
                 X + (size_t)(row0 + r) * HID + kc + k4 * 4);
        }
#pragma unroll
        for (int i = 0; i < 2; i++) {
            int idx = i * 128 + tid;
            if (idx < 192) {
                int t = idx >> 3;
                int k4 = idx & 7;
                cp16p(ws_base + st * stageW + (t * PAD + k4 * 4) * 4,
                      W + (size_t)(t < TAGS ? t : 0) * HID + kc + k4 * 4,
                      t < TAGS);
            }
        }
    };

    unsigned long long acc2[8][3];
#pragma unroll
    for (int i = 0; i < 8; i++)
#pragma unroll
        for (int j = 0; j < 3; j++) acc2[i][j] = 0ull;

    // prologue: stage 0
    load_stage(0, 0);
    cp_commit();

    for (int it = 0; it < NKC; it++) {
        const int cur = it & 1;
        if (it + 1 < NKC) {
            load_stage(cur ^ 1, (it + 1) * KC);
            cp_commit();
            cp_wait<1>();   // stage `it` complete
        } else {
            cp_wait<0>();
        }
        __syncthreads();    // data visible to all; prev compute done everywhere

#pragma unroll
        for (int k4 = 0; k4 < KC / 4; k4++) {
            ulonglong2 xv[8], wv[3];
#pragma unroll
            for (int i = 0; i < 8; i++)
                xv[i] = *(const ulonglong2*)&Xs[cur][rg + 16 * i][k4 * 4];
#pragma unroll
            for (int j = 0; j < 3; j++)
                wv[j] = *(const ulonglong2*)&Ws[cur][tg * 3 + j][k4 * 4];
#pragma unroll
            for (int i = 0; i < 8; i++)
#pragma unroll
                for (int j = 0; j < 3; j++) {
                    acc2[i][j] = ffma2(xv[i].x, wv[j].x, acc2[i][j]);
                    acc2[i][j] = ffma2(xv[i].y, wv[j].y, acc2[i][j]);
                }
        }
        __syncthreads();    // compute(it) done before buffer reuse next iter
    }

    float bb[3];
#pragma unroll
    for (int j = 0; j < 3; j++) {
        int t = tg * 3 + j;
        bb[j] = (t < TAGS) ? bias[t] : 0.f;
    }
#pragma unroll
    for (int i = 0; i < 8; i++) {
        size_t r = row0 + rg + 16 * i;
#pragma unroll
        for (int j = 0; j < 3; j++) {
            int t = tg * 3 + j;
            if (t < TAGS) {
                float2 f = unpack2(acc2[i][j]);
                float raw = f.x + f.y + bb[j];
                g_raw[r * TAGS + t] = raw;
                g_ef[r * TAGS + t] = __expf(raw);
            }
        }
    }
}

// ---------------------------------------------------------------------------
// CRF scan in scaled-probability space. One warp per batch.
// State p_t >= 0 in lane t; broadcast via smem double buffer (LDS.128 x6).
// Step: p'_t = exp(feat_t) * r * sum_j E[t][j] p_j ; r = 2^-e lane-uniform,
// recomputed every 2nd step from the shared p vector (no communication).
// Z = log(sum_t p_t * exp(trans[END][t])) + ke*ln2.
// ---------------------------------------------------------------------------
__global__ __launch_bounds__(32) void scan_kernel(
    const int* __restrict__ tags, const int* __restrict__ lengths,
    const float* __restrict__ trans, float* __restrict__ out)
{
    __shared__ __align__(16) float pbuf[2][24];
    __shared__ float fs[SEQ * TAGS];   // exp(feats) for this batch, packed 22
    __shared__ float ts[TAGS * TAGS];
    const unsigned FULL = 0xffffffffu;
    const int b = blockIdx.x;
    const int lane = threadIdx.x;
    const int len = lengths[b];

    for (int i = lane; i < TAGS * TAGS; i += 32) ts[i] = trans[i];
    {
        const float4* src = (const float4*)(g_ef + (size_t)b * SEQ * TAGS);
        float4* dst = (float4*)fs;
        const int n4 = (len * TAGS + 3) >> 2;
#pragma unroll 4
        for (int i = lane; i < n4; i += 32) dst[i] = src[i];
    }
    if (lane < 24) {
        pbuf[0][lane] = (lane == START_TAG) ? 1.f : 0.f;
        pbuf[1][lane] = 0.f;
    }
    __syncwarp();

    // E rows packed as f32x2 pairs; lane t holds E[t][0..23] (pads zero)
    unsigned long long E2[12];
    float endr = 0.f;
#pragma unroll
    for (int jp = 0; jp < 12; jp++) E2[jp] = 0ull;
    if (lane < TAGS) {
#pragma unroll
        for (int jp = 0; jp < 11; jp++) {
            float lo = __expf(ts[lane * TAGS + 2 * jp]);
            float hi = (2 * jp + 1 < TAGS) ? __expf(ts[lane * TAGS + 2 * jp + 1]) : 0.f;
            E2[jp] = pack2(lo, hi);
        }
        endr = ts[END_TAG * TAGS + lane];
    }

    float pcur = 0.f;
    int ke = 0;

    for (int i = 0; i < len; i++) {
        __syncwarp();
        const ulonglong2* pb = (const ulonglong2*)pbuf[i & 1];
        ulonglong2 v0 = pb[0], v1 = pb[1], v2 = pb[2],
                   v3 = pb[3], v4 = pb[4], v5 = pb[5];
        float ef = (lane < TAGS) ? fs[i * TAGS + lane] : 0.f;

        float r = 1.0f;
        if (i & 1) {  // renormalize: lane-uniform from shared data
            float2 a0 = unpack2(v0.x), a1 = unpack2(v0.y);
            float2 a2 = unpack2(v1.x), a3 = unpack2(v1.y);
            float2 a4 = unpack2(v2.x), a5 = unpack2(v2.y);
            float2 a6 = unpack2(v3.x), a7 = unpack2(v3.y);
            float2 a8 = unpack2(v4.x), a9 = unpack2(v4.y);
            float2 aa = unpack2(v5.x), ab = unpack2(v5.y);
            float m0 = fmaxf(fmaxf(fmaxf(a0.x, a0.y), fmaxf(a1.x, a1.y)),
                             fmaxf(fmaxf(a2.x, a2.y), fmaxf(a3.x, a3.y)));
            float m1 = fmaxf(fmaxf(fmaxf(a4.x, a4.y), fmaxf(a5.x, a5.y)),
                             fmaxf(fmaxf(a6.x, a6.y), fmaxf(a7.x, a7.y)));
            float m2 = fmaxf(fmaxf(fmaxf(a8.x, a8.y), fmaxf(a9.x, a9.y)),
                             fmaxf(fmaxf(aa.x, aa.y), fmaxf(ab.x, ab.y)));
            float m = fmaxf(m0, fmaxf(m1, m2));
            int eb = (__float_as_int(m) >> 23) & 255;
            ke += eb - 127;
            r = __int_as_float((254 - eb) << 23);  // 2^-(eb-127)
        }

        unsigned long long q0 = ffma2(E2[0], v0.x, 0ull);
        unsigned long long q1 = ffma2(E2[1], v0.y, 0ull);
        unsigned long long q2 = ffma2(E2[2], v1.x, 0ull);
        unsigned long long q3 = ffma2(E2[3], v1.y, 0ull);
        q0 = ffma2(E2[4], v2.x, q0);
        q1 = ffma2(E2[5], v2.y, q1);
        q2 = ffma2(E2[6], v3.x, q2);
        q3 = ffma2(E2[7], v3.y, q3);
        q0 = ffma2(E2[8], v4.x, q0);
        q1 = ffma2(E2[9], v4.y, q1);
        q2 = ffma2(E2[10], v5.x, q2);
        q3 = ffma2(E2[11], v5.y, q3);
        unsigned long long s2 = fadd2(fadd2(q0, q1), fadd2(q2, q3));
        float2 sf = unpack2(s2);
        float pn = (ef * r) * (sf.x + sf.y);

        if (lane < TAGS) pbuf[(i + 1) & 1][lane] = pn;
        pcur = pn;
    }

    // Z = log(sum p * exp(end_row)) + ke*ln2
    float val = (lane < TAGS) ? pcur * __expf(endr) : 0.f;
#pragma unroll
    for (int o = 16; o; o >>= 1) val += __shfl_xor_sync(FULL, val, o);
    float Z = __logf(val) + (float)ke * 0.69314718056f;

    // gold-path score (raw feats from global, transitions from smem)
    float sc = 0.f;
    const int* tgp = tags + b * SEQ;
    const float* rawb = g_raw + (size_t)b * SEQ * TAGS;
    for (int i = lane; i < len; i += 32) {
        int cur = tgp[i];
        int prev = (i == 0) ? START_TAG : tgp[i - 1];
        sc += rawb[i * TAGS + cur] + ts[cur * TAGS + prev];
    }
#pragma unroll
    for (int o = 16; o; o >>= 1) sc += __shfl_xor_sync(FULL, sc, o);

    if (lane == 0) {
        sc += ts[END_TAG * TAGS + tgp[len - 1]];
        out[b] = Z - sc;
    }
}

// ---------------------------------------------------------------------------
extern "C" void kernel_launch(void* const* d_in, const int* in_sizes, int n_in,
                              void* d_out, int out_size)
{
    const float* X       = (const float*)d_in[0];  // [128,512,1024]
    const int*   tags    = (const int*)  d_in[1];  // [128,512]
    const int*   lengths = (const int*)  d_in[2];  // [128]
    const float* W       = (const float*)d_in[3];  // [22,1024]
    const float* bias    = (const float*)d_in[4];  // [22]
    const float* trans   = (const float*)d_in[5];  // [22,22]
    float* out = (float*)d_out;                    // [128]

    gemm_kernel<<<(BATCH * SEQ) / MT, 128>>>(X, W, bias);
    scan_kernel<<<BATCH, 32>>>(tags, lengths, trans, out);
}

// round 7
// speedup vs baseline: 1.2401x; 1.0023x over previous
#include <cuda_runtime.h>
#include <cstdint>

#define TAGS 22
#define START_TAG 20
#define END_TAG 21
#define SEQ 512
#define BATCH 128
#define HID 1024

// scratch (static __device__ per allocation rules)
__device__ float g_ef[(size_t)BATCH * SEQ * TAGS];    // exp(feats), packed 22
__device__ float g_raw[(size_t)BATCH * SEQ * TAGS];   // raw feats for gold score

// ---------------- packed f32x2 helpers (Blackwell) -------------------------
__device__ __forceinline__ unsigned long long ffma2(unsigned long long a,
                                                    unsigned long long b,
                                                    unsigned long long c) {
    unsigned long long d;
    asm("fma.rn.f32x2 %0, %1, %2, %3;" : "=l"(d) : "l"(a), "l"(b), "l"(c));
    return d;
}
__device__ __forceinline__ unsigned long long fadd2(unsigned long long a,
                                                    unsigned long long b) {
    unsigned long long d;
    asm("add.rn.f32x2 %0, %1, %2;" : "=l"(d) : "l"(a), "l"(b));
    return d;
}
__device__ __forceinline__ unsigned long long pack2(float lo, float hi) {
    unsigned long long d;
    asm("mov.b64 %0, {%1, %2};" : "=l"(d) : "f"(lo), "f"(hi));
    return d;
}
__device__ __forceinline__ float2 unpack2(unsigned long long v) {
    float2 r;
    asm("mov.b64 {%0, %1}, %2;" : "=f"(r.x), "=f"(r.y) : "l"(v));
    return r;
}

// ---------------- cp.async helpers -----------------------------------------
__device__ __forceinline__ void cp16(uint32_t dst, const void* src) {
    asm volatile("cp.async.cg.shared.global [%0], [%1], 16;\n" ::
                 "r"(dst), "l"(src));
}
__device__ __forceinline__ void cp16p(uint32_t dst, const void* src, int keep) {
    // keep==0 -> copy 0 source bytes, zero-fill the 16B destination
    asm volatile("cp.async.cg.shared.global [%0], [%1], 16, %2;\n" ::
                 "r"(dst), "l"(src), "r"(keep ? 16 : 0));
}
__device__ __forceinline__ void cp_commit() {
    asm volatile("cp.async.commit_group;\n");
}
template <int N>
__device__ __forceinline__ void cp_wait() {
    asm volatile("cp.async.wait_group %0;\n" :: "n"(N));
}

// ---------------------------------------------------------------------------
// GEMM: feats[m][t] = sum_h X[m][h] * W[t][h] + bias[t]; writes raw + exp().
// 128 rows x 24 tags tile, K-chunks of 32, 2-stage cp.async pipeline.
// ---------------------------------------------------------------------------
#define MT 128
#define KC 32
#define TP 24
#define PAD 36
#define NKC (HID / KC)   // 32

__global__ __launch_bounds__(128) void gemm_kernel(
    const float* __restrict__ X, const float* __restrict__ W,
    const float* __restrict__ bias)
{
    __shared__ __align__(16) float Xs[2][MT][PAD];   // 2*18432 B
    __shared__ __align__(16) float Ws[2][TP][PAD];   // 2*3456 B
    const int tid = threadIdx.x;
    const int tg = tid & 7;    // 0..7  -> 3 tags each
    const int rg = tid >> 3;   // 0..15 -> 8 rows each
    const int row0 = blockIdx.x * MT;

    // per-thread load slots (constant across stages)
    const int xr = tid >> 3;          // via idx = i*128+tid below
    (void)xr;
    uint32_t xs_base = (uint32_t)__cvta_generic_to_shared(&Xs[0][0][0]);
    uint32_t ws_base = (uint32_t)__cvta_generic_to_shared(&Ws[0][0][0]);
    const uint32_t stageX = MT * PAD * 4;  // bytes per X stage
    const uint32_t stageW = TP * PAD * 4;

    auto load_stage = [&](int st, int kc) {
#pragma unroll
        for (int i = 0; i < 8; i++) {
            int idx = i * 128 + tid;
            int r = idx >> 3;
            int k4 = idx & 7;
            cp16(xs_base + st * stageX + (r * PAD + k4 * 4) * 4,
                 X + (size_t)(row0 + r) * HID + kc + k4 * 4);
        }
#pragma unroll
        for (int i = 0; i < 2; i++) {
            int idx = i * 128 + tid;
            if (idx < 192) {
                int t = idx >> 3;
                int k4 = idx & 7;
                cp16p(ws_base + st * stageW + (t * PAD + k4 * 4) * 4,
                      W + (size_t)(t < TAGS ? t : 0) * HID + kc + k4 * 4,
                      t < TAGS);
            }
        }
    };

    unsigned long long acc2[8][3];
#pragma unroll
    for (int i = 0; i < 8; i++)
#pragma unroll
        for (int j = 0; j < 3; j++) acc2[i][j] = 0ull;

    // prologue: stage 0
    load_stage(0, 0);
    cp_commit();

    for (int it = 0; it < NKC; it++) {
        const int cur = it & 1;
        if (it + 1 < NKC) {
            load_stage(cur ^ 1, (it + 1) * KC);
            cp_commit();
            cp_wait<1>();   // stage `it` complete
        } else {
            cp_wait<0>();
        }
        __syncthreads();    // data visible to all; prev compute done everywhere

#pragma unroll
        for (int k4 = 0; k4 < KC / 4; k4++) {
            ulonglong2 xv[8], wv[3];
#pragma unroll
            for (int i = 0; i < 8; i++)
                xv[i] = *(const ulonglong2*)&Xs[cur][rg + 16 * i][k4 * 4];
#pragma unroll
            for (int j = 0; j < 3; j++)
                wv[j] = *(const ulonglong2*)&Ws[cur][tg * 3 + j][k4 * 4];
#pragma unroll
            for (int i = 0; i < 8; i++)
#pragma unroll
                for (int j = 0; j < 3; j++) {
                    acc2[i][j] = ffma2(xv[i].x, wv[j].x, acc2[i][j]);
                    acc2[i][j] = ffma2(xv[i].y, wv[j].y, acc2[i][j]);
                }
        }
        __syncthreads();    // compute(it) done before buffer reuse next iter
    }

    float bb[3];
#pragma unroll
    for (int j = 0; j < 3; j++) {
        int t = tg * 3 + j;
        bb[j] = (t < TAGS) ? bias[t] : 0.f;
    }
#pragma unroll
    for (int i = 0; i < 8; i++) {
        size_t r = row0 + rg + 16 * i;
#pragma unroll
        for (int j = 0; j < 3; j++) {
            int t = tg * 3 + j;
            if (t < TAGS) {
                float2 f = unpack2(acc2[i][j]);
                float raw = f.x + f.y + bb[j];
                g_raw[r * TAGS + t] = raw;
                g_ef[r * TAGS + t] = __expf(raw);
            }
        }
    }
}

// ---------------------------------------------------------------------------
// CRF scan in scaled-probability space. One warp per batch.
// State p_t >= 0 in lane t; broadcast via smem double buffer (LDS.128 x6).
// Step: p'_t = exp(feat_t) * r * sum_j E[t][j] p_j ; r = 2^-e lane-uniform,
// recomputed every 2nd step from the shared p vector (no communication).
// Z = log(sum_t p_t * exp(trans[END][t])) + ke*ln2.
// ---------------------------------------------------------------------------
__global__ __launch_bounds__(32) void scan_kernel(
    const int* __restrict__ tags, const int* __restrict__ lengths,
    const float* __restrict__ trans, float* __restrict__ out)
{
    __shared__ __align__(16) float pbuf[2][24];
    __shared__ float fs[SEQ * TAGS];   // exp(feats) for this batch, packed 22
    __shared__ float ts[TAGS * TAGS];
    const unsigned FULL = 0xffffffffu;
    const int b = blockIdx.x;
    const int lane = threadIdx.x;
    const int len = lengths[b];

    for (int i = lane; i < TAGS * TAGS; i += 32) ts[i] = trans[i];
    {
        const float4* src = (const float4*)(g_ef + (size_t)b * SEQ * TAGS);
        float4* dst = (float4*)fs;
        const int n4 = (len * TAGS + 3) >> 2;
#pragma unroll 4
        for (int i = lane; i < n4; i += 32) dst[i] = src[i];
    }
    if (lane < 24) {
        pbuf[0][lane] = (lane == START_TAG) ? 1.f : 0.f;
        pbuf[1][lane] = 0.f;
    }
    __syncwarp();

    // E rows packed as f32x2 pairs; lane t holds E[t][0..23] (pads zero)
    unsigned long long E2[12];
    float endr = 0.f;
#pragma unroll
    for (int jp = 0; jp < 12; jp++) E2[jp] = 0ull;
    if (lane < TAGS) {
#pragma unroll
        for (int jp = 0; jp < 11; jp++) {
            float lo = __expf(ts[lane * TAGS + 2 * jp]);
            float hi = (2 * jp + 1 < TAGS) ? __expf(ts[lane * TAGS + 2 * jp + 1]) : 0.f;
            E2[jp] = pack2(lo, hi);
        }
        endr = ts[END_TAG * TAGS + lane];
    }

    float pcur = 0.f;
    int ke = 0;

    for (int i = 0; i < len; i++) {
        __syncwarp();
        const ulonglong2* pb = (const ulonglong2*)pbuf[i & 1];
        ulonglong2 v0 = pb[0], v1 = pb[1], v2 = pb[2],
                   v3 = pb[3], v4 = pb[4], v5 = pb[5];
        float ef = (lane < TAGS) ? fs[i * TAGS + lane] : 0.f;

        float r = 1.0f;
        if (i & 1) {  // renormalize: lane-uniform from shared data
            float2 a0 = unpack2(v0.x), a1 = unpack2(v0.y);
            float2 a2 = unpack2(v1.x), a3 = unpack2(v1.y);
            float2 a4 = unpack2(v2.x), a5 = unpack2(v2.y);
            float2 a6 = unpack2(v3.x), a7 = unpack2(v3.y);
            float2 a8 = unpack2(v4.x), a9 = unpack2(v4.y);
            float2 aa = unpack2(v5.x), ab = unpack2(v5.y);
            float m0 = fmaxf(fmaxf(fmaxf(a0.x, a0.y), fmaxf(a1.x, a1.y)),
                             fmaxf(fmaxf(a2.x, a2.y), fmaxf(a3.x, a3.y)));
            float m1 = fmaxf(fmaxf(fmaxf(a4.x, a4.y), fmaxf(a5.x, a5.y)),
                             fmaxf(fmaxf(a6.x, a6.y), fmaxf(a7.x, a7.y)));
            float m2 = fmaxf(fmaxf(fmaxf(a8.x, a8.y), fmaxf(a9.x, a9.y)),
                             fmaxf(fmaxf(aa.x, aa.y), fmaxf(ab.x, ab.y)));
            float m = fmaxf(m0, fmaxf(m1, m2));
            int eb = (__float_as_int(m) >> 23) & 255;
            ke += eb - 127;
            r = __int_as_float((254 - eb) << 23);  // 2^-(eb-127)
        }

        unsigned long long q0 = ffma2(E2[0], v0.x, 0ull);
        unsigned long long q1 = ffma2(E2[1], v0.y, 0ull);
        unsigned long long q2 = ffma2(E2[2], v1.x, 0ull);
        unsigned long long q3 = ffma2(E2[3], v1.y, 0ull);
        q0 = ffma2(E2[4], v2.x, q0);
        q1 = ffma2(E2[5], v2.y, q1);
        q2 = ffma2(E2[6], v3.x, q2);
        q3 = ffma2(E2[7], v3.y, q3);
        q0 = ffma2(E2[8], v4.x, q0);
        q1 = ffma2(E2[9], v4.y, q1);
        q2 = ffma2(E2[10], v5.x, q2);
        q3 = ffma2(E2[11], v5.y, q3);
        unsigned long long s2 = fadd2(fadd2(q0, q1), fadd2(q2, q3));
        float2 sf = unpack2(s2);
        float pn = (ef * r) * (sf.x + sf.y);

        if (lane < TAGS) pbuf[(i + 1) & 1][lane] = pn;
        pcur = pn;
    }

    // Z = log(sum p * exp(end_row)) + ke*ln2
    float val = (lane < TAGS) ? pcur * __expf(endr) : 0.f;
#pragma unroll
    for (int o = 16; o; o >>= 1) val += __shfl_xor_sync(FULL, val, o);
    float Z = __logf(val) + (float)ke * 0.69314718056f;

    // gold-path score (raw feats from global, transitions from smem)
    float sc = 0.f;
    const int* tgp = tags + b * SEQ;
    const float* rawb = g_raw + (size_t)b * SEQ * TAGS;
    for (int i = lane; i < len; i += 32) {
        int cur = tgp[i];
        int prev = (i == 0) ? START_TAG : tgp[i - 1];
        sc += rawb[i * TAGS + cur] + ts[cur * TAGS + prev];
    }
#pragma unroll
    for (int o = 16; o; o >>= 1) sc += __shfl_xor_sync(FULL, sc, o);

    if (lane == 0) {
        sc += ts[END_TAG * TAGS + tgp[len - 1]];
        out[b] = Z - sc;
    }
}

// ---------------------------------------------------------------------------
extern "C" void kernel_launch(void* const* d_in, const int* in_sizes, int n_in,
                              void* d_out, int out_size)
{
    const float* X       = (const float*)d_in[0];  // [128,512,1024]
    const int*   tags    = (const int*)  d_in[1];  // [128,512]
    const int*   lengths = (const int*)  d_in[2];  // [128]
    const float* W       = (const float*)d_in[3];  // [22,1024]
    const float* bias    = (const float*)d_in[4];  // [22]
    const float* trans   = (const float*)d_in[5];  // [22,22]
    float* out = (float*)d_out;                    // [128]

    gemm_kernel<<<(BATCH * SEQ) / MT, 128>>>(X, W, bias);
    scan_kernel<<<BATCH, 32>>>(tags, lengths, trans, out);
}